// round 1
// baseline (speedup 1.0000x reference)
#include <cuda_runtime.h>
#include <math.h>

#define NROWS 8192
#define NHALF 4096
#define DIN   512
#define DF    64      // feature dim padded (50 -> 64, zeros)
#define DOUT  50
#define HID   10
#define BM    128
#define BN    128
#define BK    16
#define NB    (NROWS/BM)   // 64

// -------- scratch (no dynamic allocation allowed) --------
__device__ float  g_Xcat[NROWS*DIN];     // 16 MB contiguous concat(Xs,Xt)
__device__ float  g_Fea [NROWS*DF];      // 2 MB padded features
__device__ float  g_onorm[NROWS];
__device__ float  g_fnorm[NROWS];
__device__ double g_acc[4];              // Sx, Sy, Smixed(2*sumKxy), Sdiag_xy
__device__ float  g_par[3];              // ep, 1/sigma, 1/sigma0

__device__ __forceinline__ float softplus_f(float x){
    return fmaxf(x, 0.f) + log1pf(expf(-fabsf(x)));
}

// ---------------- init: params + zero accumulators ----------------
__global__ void init_kernel(const float* __restrict__ eps,
                            const float* __restrict__ sig,
                            const float* __restrict__ sig0){
    if (threadIdx.x == 0){
        g_par[0] = 1.f / (1.f + expf(-eps[0]));       // ep = sigmoid(epsilonOPT)
        g_par[1] = 1.f / (sig[0]  * sig[0]);          // 1/sigma   (sigma = sigmaOPT^2)
        g_par[2] = 1.f / (sig0[0] * sig0[0]);         // 1/sigma0
        g_acc[0] = 0.0; g_acc[1] = 0.0; g_acc[2] = 0.0; g_acc[3] = 0.0;
    }
}

// ---------------- featurize: warp per row ----------------
__global__ __launch_bounds__(256)
void feat_kernel(const float* __restrict__ Xs, const float* __restrict__ Xt,
                 const float* __restrict__ W1, const float* __restrict__ b1,
                 const float* __restrict__ W2, const float* __restrict__ b2,
                 const float* __restrict__ W3, const float* __restrict__ b3,
                 const float* __restrict__ W4, const float* __restrict__ b4)
{
    __shared__ float sW1[DIN*HID];
    __shared__ float sW2[HID*HID], sW3[HID*HID], sW4[HID*DOUT];
    __shared__ float sb1[HID], sb2[HID], sb3[HID], sb4[DOUT];
    int tid = threadIdx.x;
    for (int i = tid; i < DIN*HID; i += 256) sW1[i] = W1[i];
    for (int i = tid; i < HID*HID; i += 256){ sW2[i] = W2[i]; sW3[i] = W3[i]; }
    for (int i = tid; i < HID*DOUT; i += 256) sW4[i] = W4[i];
    if (tid < HID){ sb1[tid] = b1[tid]; sb2[tid] = b2[tid]; sb3[tid] = b3[tid]; }
    if (tid < DOUT) sb4[tid] = b4[tid];
    __syncthreads();

    int warp = tid >> 5, lane = tid & 31;
    int row = blockIdx.x * 8 + warp;
    if (row >= NROWS) return;
    const float* src = (row < NHALF) ? (Xs + (size_t)row * DIN)
                                     : (Xt + (size_t)(row - NHALF) * DIN);
    float acc[HID];
    #pragma unroll
    for (int o = 0; o < HID; o++) acc[o] = 0.f;
    float on = 0.f;
    for (int k = lane; k < DIN; k += 32){
        float x = src[k];
        g_Xcat[(size_t)row * DIN + k] = x;
        on += x * x;
        #pragma unroll
        for (int o = 0; o < HID; o++) acc[o] += x * sW1[k*HID + o];
    }
    #pragma unroll
    for (int off = 16; off; off >>= 1){
        on += __shfl_xor_sync(0xffffffffu, on, off);
        #pragma unroll
        for (int o = 0; o < HID; o++)
            acc[o] += __shfl_xor_sync(0xffffffffu, acc[o], off);
    }
    if (lane == 0) g_onorm[row] = on;

    float h1[HID], h2[HID], h3[HID];
    #pragma unroll
    for (int o = 0; o < HID; o++) h1[o] = softplus_f(acc[o] + sb1[o]);
    #pragma unroll
    for (int o = 0; o < HID; o++){
        float t = sb2[o];
        #pragma unroll
        for (int p = 0; p < HID; p++) t += h1[p] * sW2[p*HID + o];
        h2[o] = softplus_f(t);
    }
    #pragma unroll
    for (int o = 0; o < HID; o++){
        float t = sb3[o];
        #pragma unroll
        for (int p = 0; p < HID; p++) t += h2[p] * sW3[p*HID + o];
        h3[o] = softplus_f(t);
    }
    float fn = 0.f;
    for (int c = lane; c < DF; c += 32){
        float v = 0.f;
        if (c < DOUT){
            v = sb4[c];
            #pragma unroll
            for (int p = 0; p < HID; p++) v += h3[p] * sW4[p*DOUT + c];
        }
        g_Fea[(size_t)row * DF + c] = v;
        fn += v * v;
    }
    #pragma unroll
    for (int off = 16; off; off >>= 1)
        fn += __shfl_xor_sync(0xffffffffu, fn, off);
    if (lane == 0) g_fnorm[row] = fn;
}

// ---------------- fused pairwise kernel ----------------
// smem: As[BK][BM] + Bs[BK][BN] + Et[BM][BN]  (4096 + 16384 floats = 80 KB)
__global__ __launch_bounds__(256, 2)
void pair_kernel(){
    int bj = blockIdx.x, bi = blockIdx.y;
    if (bj < bi) return;                       // upper-triangle tiles only
    extern __shared__ float smem[];
    float* As = smem;                          // BK*BM transposed tile
    float* Bs = smem + BK*BM;                  // BK*BN transposed tile
    float* Et = smem + 2*BK*BM;                // BM*BN e_org stage

    const int tid = threadIdx.x;
    const int tx = tid & 15, ty = tid >> 4;
    const int rowBase = bi * BM, colBase = bj * BN;
    const int lr = tid >> 2;                   // 0..63
    const int lc = (tid & 3) << 2;             // 0,4,8,12

    float acc[8][8];
    #pragma unroll
    for (int m = 0; m < 8; m++)
        #pragma unroll
        for (int n = 0; n < 8; n++) acc[m][n] = 0.f;

    // ---- phase 1: original-space Gram (K = 512) ----
    for (int kb = 0; kb < DIN; kb += BK){
        float4 a0 = *(const float4*)&g_Xcat[(size_t)(rowBase+lr   )*DIN + kb + lc];
        float4 a1 = *(const float4*)&g_Xcat[(size_t)(rowBase+lr+64)*DIN + kb + lc];
        float4 b0 = *(const float4*)&g_Xcat[(size_t)(colBase+lr   )*DIN + kb + lc];
        float4 b1 = *(const float4*)&g_Xcat[(size_t)(colBase+lr+64)*DIN + kb + lc];
        As[(lc+0)*BM + lr] = a0.x; As[(lc+1)*BM + lr] = a0.y;
        As[(lc+2)*BM + lr] = a0.z; As[(lc+3)*BM + lr] = a0.w;
        As[(lc+0)*BM + lr+64] = a1.x; As[(lc+1)*BM + lr+64] = a1.y;
        As[(lc+2)*BM + lr+64] = a1.z; As[(lc+3)*BM + lr+64] = a1.w;
        Bs[(lc+0)*BN + lr] = b0.x; Bs[(lc+1)*BN + lr] = b0.y;
        Bs[(lc+2)*BN + lr] = b0.z; Bs[(lc+3)*BN + lr] = b0.w;
        Bs[(lc+0)*BN + lr+64] = b1.x; Bs[(lc+1)*BN + lr+64] = b1.y;
        Bs[(lc+2)*BN + lr+64] = b1.z; Bs[(lc+3)*BN + lr+64] = b1.w;
        __syncthreads();
        #pragma unroll
        for (int k = 0; k < BK; k++){
            float a[8], b[8];
            #pragma unroll
            for (int m = 0; m < 8; m++) a[m] = As[k*BM + ty*8 + m];
            #pragma unroll
            for (int n = 0; n < 8; n++) b[n] = Bs[k*BN + tx*8 + n];
            #pragma unroll
            for (int m = 0; m < 8; m++)
                #pragma unroll
                for (int n = 0; n < 8; n++) acc[m][n] += a[m] * b[n];
        }
        __syncthreads();
    }

    const float ep    = g_par[0];
    const float invs  = g_par[1];
    const float invs0 = g_par[2];

    {   // convert Do -> e_org, stage to smem, clear accumulators
        float onr[8], onc[8];
        #pragma unroll
        for (int m = 0; m < 8; m++) onr[m] = g_onorm[rowBase + ty*8 + m];
        #pragma unroll
        for (int n = 0; n < 8; n++) onc[n] = g_onorm[colBase + tx*8 + n];
        #pragma unroll
        for (int m = 0; m < 8; m++)
            #pragma unroll
            for (int n = 0; n < 8; n++){
                float d = fmaxf(onr[m] + onc[n] - 2.f * acc[m][n], 0.f);
                Et[(ty*8+m)*BN + tx*8 + n] = __expf(-d * invs);
                acc[m][n] = 0.f;
            }
    }

    // ---- phase 2: feature-space Gram (K = 64 padded) ----
    for (int kb = 0; kb < DF; kb += BK){
        float4 a0 = *(const float4*)&g_Fea[(size_t)(rowBase+lr   )*DF + kb + lc];
        float4 a1 = *(const float4*)&g_Fea[(size_t)(rowBase+lr+64)*DF + kb + lc];
        float4 b0 = *(const float4*)&g_Fea[(size_t)(colBase+lr   )*DF + kb + lc];
        float4 b1 = *(const float4*)&g_Fea[(size_t)(colBase+lr+64)*DF + kb + lc];
        As[(lc+0)*BM + lr] = a0.x; As[(lc+1)*BM + lr] = a0.y;
        As[(lc+2)*BM + lr] = a0.z; As[(lc+3)*BM + lr] = a0.w;
        As[(lc+0)*BM + lr+64] = a1.x; As[(lc+1)*BM + lr+64] = a1.y;
        As[(lc+2)*BM + lr+64] = a1.z; As[(lc+3)*BM + lr+64] = a1.w;
        Bs[(lc+0)*BN + lr] = b0.x; Bs[(lc+1)*BN + lr] = b0.y;
        Bs[(lc+2)*BN + lr] = b0.z; Bs[(lc+3)*BN + lr] = b0.w;
        Bs[(lc+0)*BN + lr+64] = b1.x; Bs[(lc+1)*BN + lr+64] = b1.y;
        Bs[(lc+2)*BN + lr+64] = b1.z; Bs[(lc+3)*BN + lr+64] = b1.w;
        __syncthreads();
        #pragma unroll
        for (int k = 0; k < BK; k++){
            float a[8], b[8];
            #pragma unroll
            for (int m = 0; m < 8; m++) a[m] = As[k*BM + ty*8 + m];
            #pragma unroll
            for (int n = 0; n < 8; n++) b[n] = Bs[k*BN + tx*8 + n];
            #pragma unroll
            for (int m = 0; m < 8; m++)
                #pragma unroll
                for (int n = 0; n < 8; n++) acc[m][n] += a[m] * b[n];
        }
        __syncthreads();
    }

    // ---- epilogue: deep kernel + classified reduction ----
    float fnr[8], fnc[8];
    #pragma unroll
    for (int m = 0; m < 8; m++) fnr[m] = g_fnorm[rowBase + ty*8 + m];
    #pragma unroll
    for (int n = 0; n < 8; n++) fnc[n] = g_fnorm[colBase + tx*8 + n];

    const float mult = (bi == bj) ? 1.f : 2.f;
    float sx = 0.f, sy = 0.f, smix = 0.f, sd = 0.f;
    #pragma unroll
    for (int m = 0; m < 8; m++){
        const int ri = rowBase + ty*8 + m;
        const bool rX = ri < NHALF;
        #pragma unroll
        for (int n = 0; n < 8; n++){
            const int ci = colBase + tx*8 + n;
            if (ri == ci) continue;                      // diagonal excluded analytically
            float dd = fmaxf(fnr[m] + fnc[n] - 2.f * acc[m][n], 0.f);
            float eo = Et[(ty*8+m)*BN + tx*8 + n];
            float kv = (1.f - ep) * __expf(-dd * invs0) * eo + ep * eo;
            const bool cX = ci < NHALF;
            if (rX && cX)        sx   += kv;
            else if (!rX && !cX) sy   += kv;
            else {
                smix += kv;
                if (ci - ri == NHALF || ri - ci == NHALF) sd += kv;
            }
        }
    }
    sx *= mult; sy *= mult; smix *= mult;                // sd counted once per pair

    #pragma unroll
    for (int off = 16; off; off >>= 1){
        sx   += __shfl_xor_sync(0xffffffffu, sx,   off);
        sy   += __shfl_xor_sync(0xffffffffu, sy,   off);
        smix += __shfl_xor_sync(0xffffffffu, smix, off);
        sd   += __shfl_xor_sync(0xffffffffu, sd,   off);
    }
    if ((tid & 31) == 0){
        atomicAdd(&g_acc[0], (double)sx);
        atomicAdd(&g_acc[1], (double)sy);
        atomicAdd(&g_acc[2], (double)smix);
        atomicAdd(&g_acc[3], (double)sd);
    }
}

// ---------------- finalize ----------------
__global__ void fin_kernel(float* __restrict__ out){
    double n = (double)NHALF;
    double denom = n * (n - 1.0);
    double xx = g_acc[0] / denom;
    double yy = g_acc[1] / denom;
    double xy = (0.5 * g_acc[2] - g_acc[3]) / denom;
    out[0] = (float)(xx - 2.0 * xy + yy);
}

// ---------------- launch ----------------
extern "C" void kernel_launch(void* const* d_in, const int* in_sizes, int n_in,
                              void* d_out, int out_size){
    const float* Xs  = (const float*)d_in[0];
    const float* Xt  = (const float*)d_in[1];
    const float* W1  = (const float*)d_in[2];
    const float* b1  = (const float*)d_in[3];
    const float* W2  = (const float*)d_in[4];
    const float* b2  = (const float*)d_in[5];
    const float* W3  = (const float*)d_in[6];
    const float* b3  = (const float*)d_in[7];
    const float* W4  = (const float*)d_in[8];
    const float* b4  = (const float*)d_in[9];
    const float* eps = (const float*)d_in[10];
    const float* sg  = (const float*)d_in[11];
    const float* sg0 = (const float*)d_in[12];

    init_kernel<<<1, 32>>>(eps, sg, sg0);
    feat_kernel<<<NROWS/8, 256>>>(Xs, Xt, W1, b1, W2, b2, W3, b3, W4, b4);

    const int shmem = (2*BK*BM + BM*BN) * (int)sizeof(float);   // 80 KB
    cudaFuncSetAttribute(pair_kernel, cudaFuncAttributeMaxDynamicSharedMemorySize, shmem);
    dim3 grid(NB, NB);
    pair_kernel<<<grid, 256, shmem>>>();

    fin_kernel<<<1, 1>>>((float*)d_out);
}

// round 2
// speedup vs baseline: 2.2395x; 2.2395x over previous
#include <cuda_runtime.h>
#include <math.h>
#include <stdint.h>

#define NROWS 8192
#define NHALF 4096
#define DIN   512
#define DF    64      // feature dim padded (50 -> 64, zeros)
#define DOUT  50
#define HID   10
#define BM    128
#define BN    128
#define BK    16      // phase-2 (fp32 SIMT) k-chunk
#define KC    32      // phase-1 (tensor) k-chunk
#define LDA   36      // padded lead dim for tf32 tiles (32 + 4)
#define LDE   129     // padded lead dim for Et stage
#define NB    (NROWS/BM)   // 64

// -------- scratch (no dynamic allocation allowed) --------
__device__ float  g_Xcat[NROWS*DIN];     // 16 MB contiguous concat(Xs,Xt)
__device__ float  g_Fea [NROWS*DF];      // 2 MB padded features
__device__ float  g_onorm[NROWS];
__device__ float  g_fnorm[NROWS];
__device__ double g_acc[4];              // Sx, Sy, Smixed(2*sumKxy), Sdiag_xy
__device__ float  g_par[3];              // ep, 1/sigma, 1/sigma0

__device__ __forceinline__ float softplus_f(float x){
    return fmaxf(x, 0.f) + log1pf(expf(-fabsf(x)));
}

// exp(-x) for x >= 0, FMA-pipe only (no MUFU). ~3e-7 relative error.
__device__ __forceinline__ float exp_neg(float x){
    float t = x * -1.4426950408889634f;          // -x * log2(e)
    t = fmaxf(t, -125.f);                        // clamp: exp(-x) ~ 0 there anyway
    float fn = t + 12582912.f;                   // 2^23 + 2^22 round-to-int magic
    int   ni = __float_as_int(fn) - 0x4B400000;  // = round(t)
    float r  = t - (fn - 12582912.f);            // r in [-0.5, 0.5]
    float p  = 1.5403530393e-4f;                 // 2^r poly (ln2 Taylor, deg 6)
    p = fmaf(p, r, 1.3333558146e-3f);
    p = fmaf(p, r, 9.6181291076e-3f);
    p = fmaf(p, r, 5.5504108665e-2f);
    p = fmaf(p, r, 2.4022650696e-1f);
    p = fmaf(p, r, 6.9314718056e-1f);
    p = fmaf(p, r, 1.0f);
    return __int_as_float(__float_as_int(p) + (ni << 23));
}

__device__ __forceinline__ uint32_t cvt_tf32(float v){
    uint32_t u;
    asm("cvt.rna.tf32.f32 %0, %1;" : "=r"(u) : "f"(v));
    return u;
}

// ---------------- init: params + zero accumulators ----------------
__global__ void init_kernel(const float* __restrict__ eps,
                            const float* __restrict__ sig,
                            const float* __restrict__ sig0){
    if (threadIdx.x == 0){
        g_par[0] = 1.f / (1.f + expf(-eps[0]));       // ep = sigmoid(epsilonOPT)
        g_par[1] = 1.f / (sig[0]  * sig[0]);          // 1/sigma   (sigma = sigmaOPT^2)
        g_par[2] = 1.f / (sig0[0] * sig0[0]);         // 1/sigma0
        g_acc[0] = 0.0; g_acc[1] = 0.0; g_acc[2] = 0.0; g_acc[3] = 0.0;
    }
}

// ---------------- featurize: warp per row ----------------
__global__ __launch_bounds__(256)
void feat_kernel(const float* __restrict__ Xs, const float* __restrict__ Xt,
                 const float* __restrict__ W1, const float* __restrict__ b1,
                 const float* __restrict__ W2, const float* __restrict__ b2,
                 const float* __restrict__ W3, const float* __restrict__ b3,
                 const float* __restrict__ W4, const float* __restrict__ b4)
{
    __shared__ float sW1[DIN*HID];
    __shared__ float sW2[HID*HID], sW3[HID*HID], sW4[HID*DOUT];
    __shared__ float sb1[HID], sb2[HID], sb3[HID], sb4[DOUT];
    int tid = threadIdx.x;
    for (int i = tid; i < DIN*HID; i += 256) sW1[i] = W1[i];
    for (int i = tid; i < HID*HID; i += 256){ sW2[i] = W2[i]; sW3[i] = W3[i]; }
    for (int i = tid; i < HID*DOUT; i += 256) sW4[i] = W4[i];
    if (tid < HID){ sb1[tid] = b1[tid]; sb2[tid] = b2[tid]; sb3[tid] = b3[tid]; }
    if (tid < DOUT) sb4[tid] = b4[tid];
    __syncthreads();

    int warp = tid >> 5, lane = tid & 31;
    int row = blockIdx.x * 8 + warp;
    if (row >= NROWS) return;
    const float* src = (row < NHALF) ? (Xs + (size_t)row * DIN)
                                     : (Xt + (size_t)(row - NHALF) * DIN);
    float acc[HID];
    #pragma unroll
    for (int o = 0; o < HID; o++) acc[o] = 0.f;
    float on = 0.f;
    for (int k = lane; k < DIN; k += 32){
        float x = src[k];
        g_Xcat[(size_t)row * DIN + k] = x;
        on += x * x;
        #pragma unroll
        for (int o = 0; o < HID; o++) acc[o] += x * sW1[k*HID + o];
    }
    #pragma unroll
    for (int off = 16; off; off >>= 1){
        on += __shfl_xor_sync(0xffffffffu, on, off);
        #pragma unroll
        for (int o = 0; o < HID; o++)
            acc[o] += __shfl_xor_sync(0xffffffffu, acc[o], off);
    }
    if (lane == 0) g_onorm[row] = on;

    float h1[HID], h2[HID], h3[HID];
    #pragma unroll
    for (int o = 0; o < HID; o++) h1[o] = softplus_f(acc[o] + sb1[o]);
    #pragma unroll
    for (int o = 0; o < HID; o++){
        float t = sb2[o];
        #pragma unroll
        for (int p = 0; p < HID; p++) t += h1[p] * sW2[p*HID + o];
        h2[o] = softplus_f(t);
    }
    #pragma unroll
    for (int o = 0; o < HID; o++){
        float t = sb3[o];
        #pragma unroll
        for (int p = 0; p < HID; p++) t += h2[p] * sW3[p*HID + o];
        h3[o] = softplus_f(t);
    }
    float fn = 0.f;
    for (int c = lane; c < DF; c += 32){
        float v = 0.f;
        if (c < DOUT){
            v = sb4[c];
            #pragma unroll
            for (int p = 0; p < HID; p++) v += h3[p] * sW4[p*DOUT + c];
        }
        g_Fea[(size_t)row * DF + c] = v;
        fn += v * v;
    }
    #pragma unroll
    for (int off = 16; off; off >>= 1)
        fn += __shfl_xor_sync(0xffffffffu, fn, off);
    if (lane == 0) g_fnorm[row] = fn;
}

// ---------------- fused pairwise kernel ----------------
// smem: Ash[128][36] + Bsh[128][36] (tf32 tiles) + Et[128][129]
//     = (2*128*36 + 128*129) * 4 = 102,912 bytes
__global__ __launch_bounds__(256, 2)
void pair_kernel(){
    int bj = blockIdx.x, bi = blockIdx.y;
    if (bj < bi) return;                       // upper-triangle tiles only
    extern __shared__ float smem[];
    float* Ash = smem;                         // [128][LDA]
    float* Bsh = smem + BM*LDA;                // [128][LDA]
    float* Et  = smem + 2*BM*LDA;              // [128][LDE]

    const int tid  = threadIdx.x;
    const int lane = tid & 31, warp = tid >> 5;
    const int gid  = lane >> 2, tig = lane & 3;
    const int warpM = warp >> 1, warpN = warp & 1;   // 4 x 2 warp grid
    const int rw = warpM * 32;                 // warp row base (local)
    const int cw = warpN * 64;                 // warp col base (local)
    const int rowBase = bi * BM, colBase = bj * BN;

    // ---- phase 1: original-space Gram via tf32 tensor cores (K = 512) ----
    float acc[2][8][4];
    #pragma unroll
    for (int mi = 0; mi < 2; mi++)
        #pragma unroll
        for (int ni = 0; ni < 8; ni++)
            #pragma unroll
            for (int r = 0; r < 4; r++) acc[mi][ni][r] = 0.f;

    for (int kb = 0; kb < DIN; kb += KC){
        #pragma unroll
        for (int i = 0; i < 4; i++){
            int idx = tid + i * 256;           // 1024 float4 slots
            int r = idx >> 3, sl = (idx & 7) << 2;
            float4 va = *(const float4*)&g_Xcat[(size_t)(rowBase + r)*DIN + kb + sl];
            float4 vb = *(const float4*)&g_Xcat[(size_t)(colBase + r)*DIN + kb + sl];
            uint32_t* pa = (uint32_t*)&Ash[r*LDA + sl];
            uint32_t* pb = (uint32_t*)&Bsh[r*LDA + sl];
            pa[0] = cvt_tf32(va.x); pa[1] = cvt_tf32(va.y);
            pa[2] = cvt_tf32(va.z); pa[3] = cvt_tf32(va.w);
            pb[0] = cvt_tf32(vb.x); pb[1] = cvt_tf32(vb.y);
            pb[2] = cvt_tf32(vb.z); pb[3] = cvt_tf32(vb.w);
        }
        __syncthreads();
        #pragma unroll
        for (int ks = 0; ks < KC; ks += 8){
            uint32_t bfr[8][2];
            #pragma unroll
            for (int ni = 0; ni < 8; ni++){
                const uint32_t* bp = (const uint32_t*)&Bsh[(cw + ni*8 + gid)*LDA + ks + tig];
                bfr[ni][0] = bp[0];
                bfr[ni][1] = bp[4];
            }
            #pragma unroll
            for (int mi = 0; mi < 2; mi++){
                const uint32_t* ap0 = (const uint32_t*)&Ash[(rw + mi*16 +     gid)*LDA + ks + tig];
                const uint32_t* ap1 = (const uint32_t*)&Ash[(rw + mi*16 + 8 + gid)*LDA + ks + tig];
                uint32_t a0 = ap0[0], a1 = ap1[0], a2 = ap0[4], a3 = ap1[4];
                #pragma unroll
                for (int ni = 0; ni < 8; ni++){
                    asm volatile(
                        "mma.sync.aligned.m16n8k8.row.col.f32.tf32.tf32.f32 "
                        "{%0,%1,%2,%3}, {%4,%5,%6,%7}, {%8,%9}, {%0,%1,%2,%3};\n"
                        : "+f"(acc[mi][ni][0]), "+f"(acc[mi][ni][1]),
                          "+f"(acc[mi][ni][2]), "+f"(acc[mi][ni][3])
                        : "r"(a0), "r"(a1), "r"(a2), "r"(a3),
                          "r"(bfr[ni][0]), "r"(bfr[ni][1]));
                }
            }
        }
        __syncthreads();
    }

    const float ep    = g_par[0];
    const float invs  = g_par[1];
    const float invs0 = g_par[2];

    {   // convert Do -> e_org, stage into Et (frag layout -> (row, col))
        float rn[4], cn[16];
        #pragma unroll
        for (int mi = 0; mi < 2; mi++)
            #pragma unroll
            for (int rr = 0; rr < 2; rr++)
                rn[mi*2+rr] = g_onorm[rowBase + rw + mi*16 + rr*8 + gid];
        #pragma unroll
        for (int ni = 0; ni < 8; ni++)
            #pragma unroll
            for (int cc = 0; cc < 2; cc++)
                cn[ni*2+cc] = g_onorm[colBase + cw + ni*8 + tig*2 + cc];
        #pragma unroll
        for (int mi = 0; mi < 2; mi++)
            #pragma unroll
            for (int ni = 0; ni < 8; ni++)
                #pragma unroll
                for (int rr = 0; rr < 2; rr++)
                    #pragma unroll
                    for (int cc = 0; cc < 2; cc++){
                        int lm = rw + mi*16 + rr*8 + gid;
                        int ln = cw + ni*8 + tig*2 + cc;
                        float d = fmaxf(rn[mi*2+rr] + cn[ni*2+cc]
                                        - 2.f * acc[mi][ni][rr*2+cc], 0.f);
                        Et[lm*LDE + ln] = exp_neg(d * invs);
                    }
    }
    __syncthreads();

    // ---- phase 2: feature-space Gram, fp32 SIMT (K = 64 padded) ----
    float* As2 = smem;                 // [BK][BM] transposed tile
    float* Bs2 = smem + BK*BM;         // [BK][BN]
    const int tx = tid & 15, ty = tid >> 4;
    const int lr = tid >> 2;           // 0..63
    const int lc = (tid & 3) << 2;     // 0,4,8,12

    float fac[8][8];
    #pragma unroll
    for (int m = 0; m < 8; m++)
        #pragma unroll
        for (int n = 0; n < 8; n++) fac[m][n] = 0.f;

    for (int kb = 0; kb < DF; kb += BK){
        float4 a0 = *(const float4*)&g_Fea[(size_t)(rowBase+lr   )*DF + kb + lc];
        float4 a1 = *(const float4*)&g_Fea[(size_t)(rowBase+lr+64)*DF + kb + lc];
        float4 b0 = *(const float4*)&g_Fea[(size_t)(colBase+lr   )*DF + kb + lc];
        float4 b1 = *(const float4*)&g_Fea[(size_t)(colBase+lr+64)*DF + kb + lc];
        As2[(lc+0)*BM + lr] = a0.x; As2[(lc+1)*BM + lr] = a0.y;
        As2[(lc+2)*BM + lr] = a0.z; As2[(lc+3)*BM + lr] = a0.w;
        As2[(lc+0)*BM + lr+64] = a1.x; As2[(lc+1)*BM + lr+64] = a1.y;
        As2[(lc+2)*BM + lr+64] = a1.z; As2[(lc+3)*BM + lr+64] = a1.w;
        Bs2[(lc+0)*BN + lr] = b0.x; Bs2[(lc+1)*BN + lr] = b0.y;
        Bs2[(lc+2)*BN + lr] = b0.z; Bs2[(lc+3)*BN + lr] = b0.w;
        Bs2[(lc+0)*BN + lr+64] = b1.x; Bs2[(lc+1)*BN + lr+64] = b1.y;
        Bs2[(lc+2)*BN + lr+64] = b1.z; Bs2[(lc+3)*BN + lr+64] = b1.w;
        __syncthreads();
        #pragma unroll
        for (int k = 0; k < BK; k++){
            float a[8], b[8];
            #pragma unroll
            for (int m = 0; m < 8; m++) a[m] = As2[k*BM + ty*8 + m];
            #pragma unroll
            for (int n = 0; n < 8; n++) b[n] = Bs2[k*BN + tx*8 + n];
            #pragma unroll
            for (int m = 0; m < 8; m++)
                #pragma unroll
                for (int n = 0; n < 8; n++) fac[m][n] += a[m] * b[n];
        }
        __syncthreads();
    }

    // ---- epilogue: deep kernel + classified reduction ----
    float fnr[8], fnc[8];
    #pragma unroll
    for (int m = 0; m < 8; m++) fnr[m] = g_fnorm[rowBase + ty*8 + m];
    #pragma unroll
    for (int n = 0; n < 8; n++) fnc[n] = g_fnorm[colBase + tx*8 + n];

    const float mult = (bi == bj) ? 1.f : 2.f;
    float sx = 0.f, sy = 0.f, smix = 0.f, sd = 0.f;
    #pragma unroll
    for (int m = 0; m < 8; m++){
        const int ri = rowBase + ty*8 + m;
        const bool rX = ri < NHALF;
        #pragma unroll
        for (int n = 0; n < 8; n++){
            const int ci = colBase + tx*8 + n;
            if (ri == ci) continue;                      // diagonal excluded analytically
            float dd = fmaxf(fnr[m] + fnc[n] - 2.f * fac[m][n], 0.f);
            float eo = Et[(ty*8+m)*LDE + tx*8 + n];
            float kv = (1.f - ep) * exp_neg(dd * invs0) * eo + ep * eo;
            const bool cX = ci < NHALF;
            if (rX && cX)        sx   += kv;
            else if (!rX && !cX) sy   += kv;
            else {
                smix += kv;
                if (ci - ri == NHALF || ri - ci == NHALF) sd += kv;
            }
        }
    }
    sx *= mult; sy *= mult; smix *= mult;                // sd counted once per pair

    #pragma unroll
    for (int off = 16; off; off >>= 1){
        sx   += __shfl_xor_sync(0xffffffffu, sx,   off);
        sy   += __shfl_xor_sync(0xffffffffu, sy,   off);
        smix += __shfl_xor_sync(0xffffffffu, smix, off);
        sd   += __shfl_xor_sync(0xffffffffu, sd,   off);
    }
    if ((tid & 31) == 0){
        atomicAdd(&g_acc[0], (double)sx);
        atomicAdd(&g_acc[1], (double)sy);
        atomicAdd(&g_acc[2], (double)smix);
        atomicAdd(&g_acc[3], (double)sd);
    }
}

// ---------------- finalize ----------------
__global__ void fin_kernel(float* __restrict__ out){
    double n = (double)NHALF;
    double denom = n * (n - 1.0);
    double xx = g_acc[0] / denom;
    double yy = g_acc[1] / denom;
    double xy = (0.5 * g_acc[2] - g_acc[3]) / denom;
    out[0] = (float)(xx - 2.0 * xy + yy);
}

// ---------------- launch ----------------
extern "C" void kernel_launch(void* const* d_in, const int* in_sizes, int n_in,
                              void* d_out, int out_size){
    const float* Xs  = (const float*)d_in[0];
    const float* Xt  = (const float*)d_in[1];
    const float* W1  = (const float*)d_in[2];
    const float* b1  = (const float*)d_in[3];
    const float* W2  = (const float*)d_in[4];
    const float* b2  = (const float*)d_in[5];
    const float* W3  = (const float*)d_in[6];
    const float* b3  = (const float*)d_in[7];
    const float* W4  = (const float*)d_in[8];
    const float* b4  = (const float*)d_in[9];
    const float* eps = (const float*)d_in[10];
    const float* sg  = (const float*)d_in[11];
    const float* sg0 = (const float*)d_in[12];

    init_kernel<<<1, 32>>>(eps, sg, sg0);
    feat_kernel<<<NROWS/8, 256>>>(Xs, Xt, W1, b1, W2, b2, W3, b3, W4, b4);

    const int shmem = (2*BM*LDA + BM*LDE) * (int)sizeof(float);   // 102,912 B
    cudaFuncSetAttribute(pair_kernel, cudaFuncAttributeMaxDynamicSharedMemorySize, shmem);
    dim3 grid(NB, NB);
    pair_kernel<<<grid, 256, shmem>>>();

    fin_kernel<<<1, 1>>>((float*)d_out);
}

// round 3
// speedup vs baseline: 2.5558x; 1.1412x over previous
#include <cuda_runtime.h>
#include <math.h>
#include <stdint.h>

#define NROWS 8192
#define NHALF 4096
#define DIN   512
#define DF    64      // feature dim padded (50 -> 64, zeros)
#define DOUT  50
#define HID   10
#define BM    128
#define BN    128
#define BK    16      // phase-2 (fp32 SIMT) k-chunk
#define KC    32      // phase-1 (tensor) k-chunk
#define LDE   129     // padded lead dim for Et stage
#define NB    (NROWS/BM)   // 64
#define NCHUNK (DIN/KC)    // 16

// smem float offsets: stage0 A@0 B@4096, stage1 A@8192 B@12288 (overlaps Et),
// Et@8192 (written only after phase-1 loop). Phase-2 tiles reuse [0, 8192).
#define OFF_A0  0
#define OFF_B0  4096
#define OFF_A1  8192
#define OFF_B1  12288
#define OFF_ET  8192
#define SMEM_FLOATS (OFF_ET + BM*LDE)          // 8192 + 16512 = 24704
#define SMEM_BYTES  (SMEM_FLOATS * 4)          // 98816 B -> 2 CTAs/SM

// -------- scratch (no dynamic allocation allowed) --------
__device__ float  g_Xcat[NROWS*DIN];     // 16 MB contiguous concat(Xs,Xt)
__device__ float  g_Fea [NROWS*DF];      // 2 MB padded features
__device__ float  g_onorm[NROWS];
__device__ float  g_fnorm[NROWS];
__device__ double g_acc[4];              // Sx, Sy, Smixed(2*sumKxy), Sdiag_xy
__device__ float  g_par[3];              // ep, 1/sigma, 1/sigma0

__device__ __forceinline__ float softplus_f(float x){
    return fmaxf(x, 0.f) + log1pf(expf(-fabsf(x)));
}

// exp(-x) for x >= 0, FMA-pipe only (no MUFU). ~3e-7 relative error.
__device__ __forceinline__ float exp_neg(float x){
    float t = x * -1.4426950408889634f;          // -x * log2(e)
    t = fmaxf(t, -125.f);                        // clamp: exp(-x) ~ 0 there anyway
    float fn = t + 12582912.f;                   // 2^23 + 2^22 round-to-int magic
    int   ni = __float_as_int(fn) - 0x4B400000;  // = round(t)
    float r  = t - (fn - 12582912.f);            // r in [-0.5, 0.5]
    float p  = 1.5403530393e-4f;                 // 2^r poly (ln2 Taylor, deg 6)
    p = fmaf(p, r, 1.3333558146e-3f);
    p = fmaf(p, r, 9.6181291076e-3f);
    p = fmaf(p, r, 5.5504108665e-2f);
    p = fmaf(p, r, 2.4022650696e-1f);
    p = fmaf(p, r, 6.9314718056e-1f);
    p = fmaf(p, r, 1.0f);
    return __int_as_float(__float_as_int(p) + (ni << 23));
}

__device__ __forceinline__ void cp16(float* dst, const float* src){
    uint32_t d = (uint32_t)__cvta_generic_to_shared(dst);
    asm volatile("cp.async.cg.shared.global [%0], [%1], 16;\n"
                 :: "r"(d), "l"(src) : "memory");
}
__device__ __forceinline__ void cp_commit(){
    asm volatile("cp.async.commit_group;\n" ::: "memory");
}

// ---------------- init: params + zero accumulators ----------------
__global__ void init_kernel(const float* __restrict__ eps,
                            const float* __restrict__ sig,
                            const float* __restrict__ sig0){
    if (threadIdx.x == 0){
        g_par[0] = 1.f / (1.f + expf(-eps[0]));       // ep = sigmoid(epsilonOPT)
        g_par[1] = 1.f / (sig[0]  * sig[0]);          // 1/sigma   (sigma = sigmaOPT^2)
        g_par[2] = 1.f / (sig0[0] * sig0[0]);         // 1/sigma0
        g_acc[0] = 0.0; g_acc[1] = 0.0; g_acc[2] = 0.0; g_acc[3] = 0.0;
    }
}

// ---------------- featurize: warp per row ----------------
__global__ __launch_bounds__(256)
void feat_kernel(const float* __restrict__ Xs, const float* __restrict__ Xt,
                 const float* __restrict__ W1, const float* __restrict__ b1,
                 const float* __restrict__ W2, const float* __restrict__ b2,
                 const float* __restrict__ W3, const float* __restrict__ b3,
                 const float* __restrict__ W4, const float* __restrict__ b4)
{
    __shared__ float sW1[DIN*HID];
    __shared__ float sW2[HID*HID], sW3[HID*HID], sW4[HID*DOUT];
    __shared__ float sb1[HID], sb2[HID], sb3[HID], sb4[DOUT];
    int tid = threadIdx.x;
    for (int i = tid; i < DIN*HID; i += 256) sW1[i] = W1[i];
    for (int i = tid; i < HID*HID; i += 256){ sW2[i] = W2[i]; sW3[i] = W3[i]; }
    for (int i = tid; i < HID*DOUT; i += 256) sW4[i] = W4[i];
    if (tid < HID){ sb1[tid] = b1[tid]; sb2[tid] = b2[tid]; sb3[tid] = b3[tid]; }
    if (tid < DOUT) sb4[tid] = b4[tid];
    __syncthreads();

    int warp = tid >> 5, lane = tid & 31;
    int row = blockIdx.x * 8 + warp;
    if (row >= NROWS) return;
    const float* src = (row < NHALF) ? (Xs + (size_t)row * DIN)
                                     : (Xt + (size_t)(row - NHALF) * DIN);
    float acc[HID];
    #pragma unroll
    for (int o = 0; o < HID; o++) acc[o] = 0.f;
    float on = 0.f;
    for (int k = lane; k < DIN; k += 32){
        float x = src[k];
        g_Xcat[(size_t)row * DIN + k] = x;
        on += x * x;
        #pragma unroll
        for (int o = 0; o < HID; o++) acc[o] += x * sW1[k*HID + o];
    }
    #pragma unroll
    for (int off = 16; off; off >>= 1){
        on += __shfl_xor_sync(0xffffffffu, on, off);
        #pragma unroll
        for (int o = 0; o < HID; o++)
            acc[o] += __shfl_xor_sync(0xffffffffu, acc[o], off);
    }
    if (lane == 0) g_onorm[row] = on;

    float h1[HID], h2[HID], h3[HID];
    #pragma unroll
    for (int o = 0; o < HID; o++) h1[o] = softplus_f(acc[o] + sb1[o]);
    #pragma unroll
    for (int o = 0; o < HID; o++){
        float t = sb2[o];
        #pragma unroll
        for (int p = 0; p < HID; p++) t += h1[p] * sW2[p*HID + o];
        h2[o] = softplus_f(t);
    }
    #pragma unroll
    for (int o = 0; o < HID; o++){
        float t = sb3[o];
        #pragma unroll
        for (int p = 0; p < HID; p++) t += h2[p] * sW3[p*HID + o];
        h3[o] = softplus_f(t);
    }
    float fn = 0.f;
    for (int c = lane; c < DF; c += 32){
        float v = 0.f;
        if (c < DOUT){
            v = sb4[c];
            #pragma unroll
            for (int p = 0; p < HID; p++) v += h3[p] * sW4[p*DOUT + c];
        }
        g_Fea[(size_t)row * DF + c] = v;
        fn += v * v;
    }
    #pragma unroll
    for (int off = 16; off; off >>= 1)
        fn += __shfl_xor_sync(0xffffffffu, fn, off);
    if (lane == 0) g_fnorm[row] = fn;
}

// ---------------- fused pairwise kernel ----------------
__global__ __launch_bounds__(256, 2)
void pair_kernel(){
    int bj = blockIdx.x, bi = blockIdx.y;
    if (bj < bi) return;                       // upper-triangle tiles only
    extern __shared__ float smem[];

    const int tid  = threadIdx.x;
    const int lane = tid & 31, warp = tid >> 5;
    const int gid  = lane >> 2, tig = lane & 3;
    const int warpM = warp >> 1, warpN = warp & 1;   // 4 x 2 warp grid
    const int rw = warpM * 32;                 // warp row base (local)
    const int cw = warpN * 64;                 // warp col base (local)
    const int rowBase = bi * BM, colBase = bj * BN;

    // ---- phase 1: original-space Gram via tf32 tensor cores (K = 512) ----
    // XOR-swizzled tiles: row stride 32 floats (128B); 16B granule g' = g ^ (row&7).
    // cp.async.cg loads raw fp32; HMMA.tf32 ignores low mantissa bits (truncation).
    float acc[2][8][4];
    #pragma unroll
    for (int mi = 0; mi < 2; mi++)
        #pragma unroll
        for (int ni = 0; ni < 8; ni++)
            #pragma unroll
            for (int r = 0; r < 4; r++) acc[mi][ni][r] = 0.f;

    // prefetch chunks 0 and 1
    #pragma unroll
    for (int st = 0; st < 2; st++){
        float* bA = smem + (st ? OFF_A1 : OFF_A0);
        float* bB = smem + (st ? OFF_B1 : OFF_B0);
        int kb = st * KC;
        #pragma unroll
        for (int i = 0; i < 4; i++){
            int idx = tid + i * 256;           // 1024 16B-slots per tile
            int r = idx >> 3, g = idx & 7;
            int sw = r*32 + (((g ^ (r & 7)) << 2));
            cp16(bA + sw, &g_Xcat[(size_t)(rowBase + r)*DIN + kb + (g << 2)]);
            cp16(bB + sw, &g_Xcat[(size_t)(colBase + r)*DIN + kb + (g << 2)]);
        }
        cp_commit();
    }

    for (int c = 0; c < NCHUNK; c++){
        if (c < NCHUNK - 1) asm volatile("cp.async.wait_group 1;\n" ::: "memory");
        else                asm volatile("cp.async.wait_group 0;\n" ::: "memory");
        __syncthreads();

        const float* Ash = smem + ((c & 1) ? OFF_A1 : OFF_A0);
        const float* Bsh = smem + ((c & 1) ? OFF_B1 : OFF_B0);

        #pragma unroll
        for (int ks = 0; ks < KC; ks += 8){
            const int ga = ks >> 2, gb = ga + 1;
            const int ca = ((ga ^ gid) << 2) + tig;
            const int cb = ((gb ^ gid) << 2) + tig;
            uint32_t bfr[8][2];
            #pragma unroll
            for (int ni = 0; ni < 8; ni++){
                int rb = (cw + ni*8 + gid) * 32;
                bfr[ni][0] = __float_as_uint(Bsh[rb + ca]);
                bfr[ni][1] = __float_as_uint(Bsh[rb + cb]);
            }
            #pragma unroll
            for (int mi = 0; mi < 2; mi++){
                int r0 = (rw + mi*16 +     gid) * 32;
                int r1 = (rw + mi*16 + 8 + gid) * 32;
                uint32_t a0 = __float_as_uint(Ash[r0 + ca]);
                uint32_t a1 = __float_as_uint(Ash[r1 + ca]);
                uint32_t a2 = __float_as_uint(Ash[r0 + cb]);
                uint32_t a3 = __float_as_uint(Ash[r1 + cb]);
                #pragma unroll
                for (int ni = 0; ni < 8; ni++){
                    asm volatile(
                        "mma.sync.aligned.m16n8k8.row.col.f32.tf32.tf32.f32 "
                        "{%0,%1,%2,%3}, {%4,%5,%6,%7}, {%8,%9}, {%0,%1,%2,%3};\n"
                        : "+f"(acc[mi][ni][0]), "+f"(acc[mi][ni][1]),
                          "+f"(acc[mi][ni][2]), "+f"(acc[mi][ni][3])
                        : "r"(a0), "r"(a1), "r"(a2), "r"(a3),
                          "r"(bfr[ni][0]), "r"(bfr[ni][1]));
                }
            }
        }
        __syncthreads();     // all warps done reading buf[c&1] before refill

        if (c + 2 < NCHUNK){
            float* bA = smem + ((c & 1) ? OFF_A1 : OFF_A0);
            float* bB = smem + ((c & 1) ? OFF_B1 : OFF_B0);
            int kb = (c + 2) * KC;
            #pragma unroll
            for (int i = 0; i < 4; i++){
                int idx = tid + i * 256;
                int r = idx >> 3, g = idx & 7;
                int sw = r*32 + (((g ^ (r & 7)) << 2));
                cp16(bA + sw, &g_Xcat[(size_t)(rowBase + r)*DIN + kb + (g << 2)]);
                cp16(bB + sw, &g_Xcat[(size_t)(colBase + r)*DIN + kb + (g << 2)]);
            }
            cp_commit();
        }
    }

    const float ep    = g_par[0];
    const float invs  = g_par[1];
    const float invs0 = g_par[2];
    float* Et = smem + OFF_ET;                 // [128][LDE]

    {   // convert Do -> e_org, stage into Et (frag layout -> (row, col))
        float rn[4], cn[16];
        #pragma unroll
        for (int mi = 0; mi < 2; mi++)
            #pragma unroll
            for (int rr = 0; rr < 2; rr++)
                rn[mi*2+rr] = g_onorm[rowBase + rw + mi*16 + rr*8 + gid];
        #pragma unroll
        for (int ni = 0; ni < 8; ni++)
            #pragma unroll
            for (int cc = 0; cc < 2; cc++)
                cn[ni*2+cc] = g_onorm[colBase + cw + ni*8 + tig*2 + cc];
        #pragma unroll
        for (int mi = 0; mi < 2; mi++)
            #pragma unroll
            for (int ni = 0; ni < 8; ni++)
                #pragma unroll
                for (int rr = 0; rr < 2; rr++)
                    #pragma unroll
                    for (int cc = 0; cc < 2; cc++){
                        int lm = rw + mi*16 + rr*8 + gid;
                        int ln = cw + ni*8 + tig*2 + cc;
                        float d = fmaxf(rn[mi*2+rr] + cn[ni*2+cc]
                                        - 2.f * acc[mi][ni][rr*2+cc], 0.f);
                        Et[lm*LDE + ln] = exp_neg(d * invs);
                    }
    }
    __syncthreads();

    // ---- phase 2: feature-space Gram, fp32 SIMT (K = 64 padded) ----
    float* As2 = smem;                 // [BK][BM] transposed tile
    float* Bs2 = smem + BK*BM;         // [BK][BN]
    const int tx = tid & 15, ty = tid >> 4;
    const int lr = tid >> 2;           // 0..63
    const int lc = (tid & 3) << 2;     // 0,4,8,12

    float fac[8][8];
    #pragma unroll
    for (int m = 0; m < 8; m++)
        #pragma unroll
        for (int n = 0; n < 8; n++) fac[m][n] = 0.f;

    for (int kb = 0; kb < DF; kb += BK){
        float4 a0 = *(const float4*)&g_Fea[(size_t)(rowBase+lr   )*DF + kb + lc];
        float4 a1 = *(const float4*)&g_Fea[(size_t)(rowBase+lr+64)*DF + kb + lc];
        float4 b0 = *(const float4*)&g_Fea[(size_t)(colBase+lr   )*DF + kb + lc];
        float4 b1 = *(const float4*)&g_Fea[(size_t)(colBase+lr+64)*DF + kb + lc];
        As2[(lc+0)*BM + lr] = a0.x; As2[(lc+1)*BM + lr] = a0.y;
        As2[(lc+2)*BM + lr] = a0.z; As2[(lc+3)*BM + lr] = a0.w;
        As2[(lc+0)*BM + lr+64] = a1.x; As2[(lc+1)*BM + lr+64] = a1.y;
        As2[(lc+2)*BM + lr+64] = a1.z; As2[(lc+3)*BM + lr+64] = a1.w;
        Bs2[(lc+0)*BN + lr] = b0.x; Bs2[(lc+1)*BN + lr] = b0.y;
        Bs2[(lc+2)*BN + lr] = b0.z; Bs2[(lc+3)*BN + lr] = b0.w;
        Bs2[(lc+0)*BN + lr+64] = b1.x; Bs2[(lc+1)*BN + lr+64] = b1.y;
        Bs2[(lc+2)*BN + lr+64] = b1.z; Bs2[(lc+3)*BN + lr+64] = b1.w;
        __syncthreads();
        #pragma unroll
        for (int k = 0; k < BK; k++){
            float a[8], b[8];
            #pragma unroll
            for (int m = 0; m < 8; m++) a[m] = As2[k*BM + ty*8 + m];
            #pragma unroll
            for (int n = 0; n < 8; n++) b[n] = Bs2[k*BN + tx*8 + n];
            #pragma unroll
            for (int m = 0; m < 8; m++)
                #pragma unroll
                for (int n = 0; n < 8; n++) fac[m][n] += a[m] * b[n];
        }
        __syncthreads();
    }

    // ---- epilogue: deep kernel + classified reduction ----
    float fnr[8], fnc[8];
    #pragma unroll
    for (int m = 0; m < 8; m++) fnr[m] = g_fnorm[rowBase + ty*8 + m];
    #pragma unroll
    for (int n = 0; n < 8; n++) fnc[n] = g_fnorm[colBase + tx*8 + n];

    const float mult = (bi == bj) ? 1.f : 2.f;
    float sx = 0.f, sy = 0.f, smix = 0.f, sd = 0.f;
    #pragma unroll
    for (int m = 0; m < 8; m++){
        const int ri = rowBase + ty*8 + m;
        const bool rX = ri < NHALF;
        #pragma unroll
        for (int n = 0; n < 8; n++){
            const int ci = colBase + tx*8 + n;
            if (ri == ci) continue;                      // diagonal excluded analytically
            float dd = fmaxf(fnr[m] + fnc[n] - 2.f * fac[m][n], 0.f);
            float eo = Et[(ty*8+m)*LDE + tx*8 + n];
            float kv = (1.f - ep) * exp_neg(dd * invs0) * eo + ep * eo;
            const bool cX = ci < NHALF;
            if (rX && cX)        sx   += kv;
            else if (!rX && !cX) sy   += kv;
            else {
                smix += kv;
                if (ci - ri == NHALF || ri - ci == NHALF) sd += kv;
            }
        }
    }
    sx *= mult; sy *= mult; smix *= mult;                // sd counted once per pair

    #pragma unroll
    for (int off = 16; off; off >>= 1){
        sx   += __shfl_xor_sync(0xffffffffu, sx,   off);
        sy   += __shfl_xor_sync(0xffffffffu, sy,   off);
        smix += __shfl_xor_sync(0xffffffffu, smix, off);
        sd   += __shfl_xor_sync(0xffffffffu, sd,   off);
    }
    if ((tid & 31) == 0){
        atomicAdd(&g_acc[0], (double)sx);
        atomicAdd(&g_acc[1], (double)sy);
        atomicAdd(&g_acc[2], (double)smix);
        atomicAdd(&g_acc[3], (double)sd);
    }
}

// ---------------- finalize ----------------
__global__ void fin_kernel(float* __restrict__ out){
    double n = (double)NHALF;
    double denom = n * (n - 1.0);
    double xx = g_acc[0] / denom;
    double yy = g_acc[1] / denom;
    double xy = (0.5 * g_acc[2] - g_acc[3]) / denom;
    out[0] = (float)(xx - 2.0 * xy + yy);
}

// ---------------- launch ----------------
extern "C" void kernel_launch(void* const* d_in, const int* in_sizes, int n_in,
                              void* d_out, int out_size){
    const float* Xs  = (const float*)d_in[0];
    const float* Xt  = (const float*)d_in[1];
    const float* W1  = (const float*)d_in[2];
    const float* b1  = (const float*)d_in[3];
    const float* W2  = (const float*)d_in[4];
    const float* b2  = (const float*)d_in[5];
    const float* W3  = (const float*)d_in[6];
    const float* b3  = (const float*)d_in[7];
    const float* W4  = (const float*)d_in[8];
    const float* b4  = (const float*)d_in[9];
    const float* eps = (const float*)d_in[10];
    const float* sg  = (const float*)d_in[11];
    const float* sg0 = (const float*)d_in[12];

    init_kernel<<<1, 32>>>(eps, sg, sg0);
    feat_kernel<<<NROWS/8, 256>>>(Xs, Xt, W1, b1, W2, b2, W3, b3, W4, b4);

    cudaFuncSetAttribute(pair_kernel, cudaFuncAttributeMaxDynamicSharedMemorySize, SMEM_BYTES);
    dim3 grid(NB, NB);
    pair_kernel<<<grid, 256, SMEM_BYTES>>>();

    fin_kernel<<<1, 1>>>((float*)d_out);
}